// round 1
// baseline (speedup 1.0000x reference)
#include <cuda_runtime.h>
#include <cuda_bf16.h>
#include <math.h>
#include <stdint.h>

// Problem shape (fixed by the dataset): N=65536, P=2048, D=64, 10 classes.
#define NMAX 65536
#define PMAX 2048
#define DDIM 64
#define BM 128
#define BN 128
#define LDSS 72           // bf16 elements per smem row (64 + 8 pad -> conflict-free frag loads)

// Scratch (allocation-free rule: __device__ globals)
__device__ __align__(16) __nv_bfloat16 g_xb[NMAX * DDIM];
__device__ __align__(16) __nv_bfloat16 g_pb[PMAX * DDIM];
__device__ float g_x2[NMAX];
__device__ float g_p2[PMAX];
__device__ float g_partial[NMAX / BM];

// ---------------------------------------------------------------------------
// Prologue: fp32 rows -> bf16 rows + row sum-of-squares. One warp per row.
// ---------------------------------------------------------------------------
__global__ void prep_kernel(const float* __restrict__ in, int rows, int isX) {
    int warp = (blockIdx.x * blockDim.x + threadIdx.x) >> 5;
    int lane = threadIdx.x & 31;
    if (warp >= rows) return;
    float2 v = ((const float2*)(in + (size_t)warp * DDIM))[lane];
    float ss = v.x * v.x + v.y * v.y;
    #pragma unroll
    for (int o = 16; o; o >>= 1) ss += __shfl_xor_sync(0xffffffffu, ss, o);
    __nv_bfloat162 b = __floats2bfloat162_rn(v.x, v.y);
    __nv_bfloat162* ob = isX ? (__nv_bfloat162*)g_xb : (__nv_bfloat162*)g_pb;
    ob[(size_t)warp * (DDIM / 2) + lane] = b;
    if (lane == 0) {
        float* o2 = isX ? g_x2 : g_p2;
        o2[warp] = ss;
    }
}

// ---------------------------------------------------------------------------
// Main: 128x128 tile GEMM (bf16 mma.sync) fused with masked min reduction.
// 8 warps as 4(m) x 2(n); warp tile 32x64; m16n8k16 frags.
// Track min over s = p2 - 2*dot  (monotone in distance; add x2 + sqrt at end).
// ---------------------------------------------------------------------------
__global__ __launch_bounds__(256) void glvq_main(
    const int* __restrict__ y, const int* __restrict__ plab, int N, int P) {

    __shared__ __nv_bfloat16 xs[BM * LDSS];
    __shared__ __nv_bfloat16 ps[BN * LDSS];
    __shared__ float p2s[BN];
    __shared__ int pls[BN];
    __shared__ float red[2][2][BM];  // [wn][pos/neg][row]
    __shared__ float rsum[8];

    const int tid = threadIdx.x;
    const int warp = tid >> 5, lane = tid & 31;
    const int wm = warp >> 1, wn = warp & 1;
    const int qid = lane >> 2, qtr = lane & 3;
    const int rowBase = blockIdx.x * BM;

    // Load x tile (contiguous 16KB) into padded smem.
    {
        const uint4* src = (const uint4*)(g_xb + (size_t)rowBase * DDIM);
        uint4* dst = (uint4*)xs;
        #pragma unroll
        for (int i = 0; i < 4; i++) {
            int idx = tid + i * 256;
            dst[(idx >> 3) * 9 + (idx & 7)] = src[idx];
        }
    }

    // This thread's 4 row labels (m16n8: rows qid and qid+8 per 16-row frag).
    int yv[2][2];
    #pragma unroll
    for (int mf = 0; mf < 2; mf++)
        #pragma unroll
        for (int h = 0; h < 2; h++)
            yv[mf][h] = y[rowBase + wm * 32 + mf * 16 + h * 8 + qid];

    float pmin[2][2], nmin[2][2];
    #pragma unroll
    for (int mf = 0; mf < 2; mf++)
        #pragma unroll
        for (int h = 0; h < 2; h++) { pmin[mf][h] = 1e30f; nmin[mf][h] = 1e30f; }

    for (int nt = 0; nt < P; nt += BN) {
        __syncthreads();  // protects xs store (first iter) and prior ps usage
        {
            const uint4* src = (const uint4*)(g_pb + (size_t)nt * DDIM);
            uint4* dst = (uint4*)ps;
            #pragma unroll
            for (int i = 0; i < 4; i++) {
                int idx = tid + i * 256;
                dst[(idx >> 3) * 9 + (idx & 7)] = src[idx];
            }
        }
        if (tid < BN) { p2s[tid] = g_p2[nt + tid]; pls[tid] = plab[nt + tid]; }
        __syncthreads();

        float c[16][4];
        #pragma unroll
        for (int i = 0; i < 16; i++)
            #pragma unroll
            for (int j = 0; j < 4; j++) c[i][j] = 0.f;

        #pragma unroll
        for (int kk = 0; kk < 4; kk++) {
            const int k0 = kk * 16 + qtr * 2;
            uint32_t a[2][4];
            #pragma unroll
            for (int mf = 0; mf < 2; mf++) {
                const __nv_bfloat16* ab = xs + (wm * 32 + mf * 16 + qid) * LDSS + k0;
                a[mf][0] = *(const uint32_t*)(ab);
                a[mf][1] = *(const uint32_t*)(ab + 8 * LDSS);
                a[mf][2] = *(const uint32_t*)(ab + 8);
                a[mf][3] = *(const uint32_t*)(ab + 8 * LDSS + 8);
            }
            #pragma unroll
            for (int nf = 0; nf < 8; nf++) {
                const __nv_bfloat16* bb = ps + (wn * 64 + nf * 8 + qid) * LDSS + k0;
                uint32_t b0 = *(const uint32_t*)(bb);
                uint32_t b1 = *(const uint32_t*)(bb + 8);
                #pragma unroll
                for (int mf = 0; mf < 2; mf++) {
                    float* cc = c[mf * 8 + nf];
                    asm volatile(
                        "mma.sync.aligned.m16n8k16.row.col.f32.bf16.bf16.f32 "
                        "{%0,%1,%2,%3}, {%4,%5,%6,%7}, {%8,%9}, {%0,%1,%2,%3};\n"
                        : "+f"(cc[0]), "+f"(cc[1]), "+f"(cc[2]), "+f"(cc[3])
                        : "r"(a[mf][0]), "r"(a[mf][1]), "r"(a[mf][2]), "r"(a[mf][3]),
                          "r"(b0), "r"(b1));
                }
            }
        }

        // Fused epilogue: s = p2 - 2*dot; masked running mins.
        #pragma unroll
        for (int nf = 0; nf < 8; nf++) {
            const int jc = wn * 64 + nf * 8 + qtr * 2;
            float2 pp = *(const float2*)(p2s + jc);
            int2 ll = *(const int2*)(pls + jc);
            #pragma unroll
            for (int mf = 0; mf < 2; mf++) {
                float* cc = c[mf * 8 + nf];
                float s00 = fmaf(-2.f, cc[0], pp.x);
                float s01 = fmaf(-2.f, cc[1], pp.y);
                float s10 = fmaf(-2.f, cc[2], pp.x);
                float s11 = fmaf(-2.f, cc[3], pp.y);
                if (ll.x == yv[mf][0]) pmin[mf][0] = fminf(pmin[mf][0], s00);
                else                   nmin[mf][0] = fminf(nmin[mf][0], s00);
                if (ll.y == yv[mf][0]) pmin[mf][0] = fminf(pmin[mf][0], s01);
                else                   nmin[mf][0] = fminf(nmin[mf][0], s01);
                if (ll.x == yv[mf][1]) pmin[mf][1] = fminf(pmin[mf][1], s10);
                else                   nmin[mf][1] = fminf(nmin[mf][1], s10);
                if (ll.y == yv[mf][1]) pmin[mf][1] = fminf(pmin[mf][1], s11);
                else                   nmin[mf][1] = fminf(nmin[mf][1], s11);
            }
        }
    }

    // Reduce across the 4 lanes of each quad (same rows, different cols).
    #pragma unroll
    for (int mf = 0; mf < 2; mf++)
        #pragma unroll
        for (int h = 0; h < 2; h++) {
            #pragma unroll
            for (int o = 1; o <= 2; o <<= 1) {
                pmin[mf][h] = fminf(pmin[mf][h], __shfl_xor_sync(0xffffffffu, pmin[mf][h], o));
                nmin[mf][h] = fminf(nmin[mf][h], __shfl_xor_sync(0xffffffffu, nmin[mf][h], o));
            }
        }
    if (qtr == 0) {
        #pragma unroll
        for (int mf = 0; mf < 2; mf++)
            #pragma unroll
            for (int h = 0; h < 2; h++) {
                int r = wm * 32 + mf * 16 + h * 8 + qid;
                red[wn][0][r] = pmin[mf][h];
                red[wn][1][r] = nmin[mf][h];
            }
    }
    __syncthreads();

    float mysum = 0.f;
    if (tid < BM) {
        float sp = fminf(red[0][0][tid], red[1][0][tid]);
        float sn = fminf(red[0][1][tid], red[1][1][tid]);
        float x2 = g_x2[rowBase + tid];
        float pos = sqrtf(fmaxf(sp + x2, 0.f));
        float neg = sqrtf(fmaxf(sn + x2, 0.f));
        float mu = (pos - neg) / (pos + neg);
        mysum = 1.f / (1.f + expf(-mu));
    }
    #pragma unroll
    for (int o = 16; o; o >>= 1) mysum += __shfl_xor_sync(0xffffffffu, mysum, o);
    if (lane == 0) rsum[warp] = mysum;
    __syncthreads();
    if (tid < 8) {
        float s = rsum[tid];
        #pragma unroll
        for (int o = 4; o; o >>= 1) s += __shfl_xor_sync(0xffu, s, o);
        if (tid == 0) g_partial[blockIdx.x] = s;
    }
}

// ---------------------------------------------------------------------------
// Final deterministic reduction: sum partials, divide by N.
// ---------------------------------------------------------------------------
__global__ void finish_kernel(float* __restrict__ out, int nblocks, float invN) {
    __shared__ float sb[8];
    float s = 0.f;
    for (int i = threadIdx.x; i < nblocks; i += 256) s += g_partial[i];
    #pragma unroll
    for (int o = 16; o; o >>= 1) s += __shfl_xor_sync(0xffffffffu, s, o);
    if ((threadIdx.x & 31) == 0) sb[threadIdx.x >> 5] = s;
    __syncthreads();
    if (threadIdx.x < 8) {
        float v = sb[threadIdx.x];
        #pragma unroll
        for (int o = 4; o; o >>= 1) v += __shfl_xor_sync(0xffu, v, o);
        if (threadIdx.x == 0) out[0] = v * invN;
    }
}

extern "C" void kernel_launch(void* const* d_in, const int* in_sizes, int n_in,
                              void* d_out, int out_size) {
    const float* x    = (const float*)d_in[0];
    const int*   y    = (const int*)d_in[1];
    const float* prot = (const float*)d_in[2];
    const int*   plab = (const int*)d_in[3];
    float* out = (float*)d_out;

    const int N = in_sizes[1];   // 65536
    const int P = in_sizes[3];   // 2048

    // Prologue: bf16 conversion + row norms (one warp per row, 8 warps/block).
    prep_kernel<<<N / 8, 256>>>(x, N, 1);
    prep_kernel<<<(P + 7) / 8, 256>>>(prot, P, 0);

    // Fused GEMM + masked min + per-row loss, one partial per 128-row block.
    glvq_main<<<N / BM, 256>>>(y, plab, N, P);

    // Scalar mean.
    finish_kernel<<<1, 256>>>(out, N / BM, 1.0f / (float)N);
}

// round 2
// speedup vs baseline: 1.0980x; 1.0980x over previous
#include <cuda_runtime.h>
#include <cuda_bf16.h>
#include <math.h>
#include <stdint.h>

// Problem shape (fixed by dataset): N=65536, P=2048, D=64, 10 classes.
#define NPTS 65536
#define PPTS 2048
#define DDIM 64
#define BM 128
#define BN 128
#define LDSS 72            // bf16 per smem row (64 + 8 pad): conflict-free ldmatrix
#define NTILES (PPTS / BN) // 16
#define NBLOCKS (NPTS / BM)

// Scratch (__device__ globals: allocation-free rule)
__device__ __align__(16) __nv_bfloat16 g_xb[NPTS * DDIM];
__device__ __align__(16) __nv_bfloat16 g_pb[PPTS * DDIM];
__device__ float g_x2[NPTS];
__device__ float g_p2[PPTS];
__device__ float g_partial[NBLOCKS];
__device__ unsigned int g_count; // zero-init; last block resets

// Dynamic smem layout (bytes)
#define SM_XS    0
#define SM_PS    (BM * LDSS * 2)                  // 18432
#define SM_P2    (SM_PS + 2 * BM * LDSS * 2)      // 18432 + 36864 = 55296
#define SM_PL    (SM_P2 + PPTS * 4)               // 63488
#define SM_RED   (SM_PL + PPTS * 4)               // 71680
#define SM_RSUM  (SM_RED + 2 * 2 * BM * 4)        // 75776
#define SM_FLAG  (SM_RSUM + 32)                   // 75808
#define SM_TOTAL 75840

__device__ __forceinline__ void cp16(void* dst, const void* src) {
    uint32_t d = (uint32_t)__cvta_generic_to_shared(dst);
    asm volatile("cp.async.cg.shared.global [%0], [%1], 16;\n" :: "r"(d), "l"(src));
}
#define CP_COMMIT() asm volatile("cp.async.commit_group;\n" ::: "memory")
#define CP_WAIT(n)  asm volatile("cp.async.wait_group %0;\n" :: "n"(n) : "memory")

// ---------------------------------------------------------------------------
// Prep: fp32 rows (x then prototypes) -> bf16 rows + row sum-of-squares.
// One warp per row. Single kernel for both tensors.
// ---------------------------------------------------------------------------
__global__ void prep_kernel(const float* __restrict__ x,
                            const float* __restrict__ p, int N, int P) {
    int warp = (blockIdx.x * blockDim.x + threadIdx.x) >> 5;
    int lane = threadIdx.x & 31;
    if (warp >= N + P) return;
    const float* src; __nv_bfloat162* db; float* d2; int r;
    if (warp < N) { r = warp;     src = x; db = (__nv_bfloat162*)g_xb; d2 = g_x2; }
    else          { r = warp - N; src = p; db = (__nv_bfloat162*)g_pb; d2 = g_p2; }
    float2 v = ((const float2*)(src + (size_t)r * DDIM))[lane];
    float ss = v.x * v.x + v.y * v.y;
    #pragma unroll
    for (int o = 16; o; o >>= 1) ss += __shfl_xor_sync(0xffffffffu, ss, o);
    db[(size_t)r * (DDIM / 2) + lane] = __floats2bfloat162_rn(v.x, v.y);
    if (lane == 0) d2[r] = ss;
}

// ---------------------------------------------------------------------------
// Main: 128x128-tile bf16 mma.sync GEMM fused with masked min + loss.
// 8 warps = 4(m) x 2(n); warp tile 32x64. A frags hoisted out of P-loop.
// cp.async double-buffered B tiles. Track min over s = p^2 - 2*dot.
// Last-finished block performs the deterministic final mean.
// ---------------------------------------------------------------------------
__global__ __launch_bounds__(256, 2) void glvq_main(
    const int* __restrict__ y, const int* __restrict__ plab,
    float* __restrict__ out) {

    extern __shared__ char sm[];
    __nv_bfloat16* xs  = (__nv_bfloat16*)(sm + SM_XS);
    __nv_bfloat16* ps  = (__nv_bfloat16*)(sm + SM_PS);
    float*         p2s = (float*)(sm + SM_P2);
    int*           pls = (int*)(sm + SM_PL);
    float*         red = (float*)(sm + SM_RED);
    float*         rsum = (float*)(sm + SM_RSUM);
    int*           flag = (int*)(sm + SM_FLAG);

    const int tid = threadIdx.x;
    const int warp = tid >> 5, lane = tid & 31;
    const int wm = warp >> 1, wn = warp & 1;
    const int qid = lane >> 2, qtr = lane & 3;
    const int rowBase = blockIdx.x * BM;

    // Stage x tile (group 0)
    {
        const char* src = (const char*)(g_xb + (size_t)rowBase * DDIM);
        uint4* dst = (uint4*)xs;
        #pragma unroll
        for (int i = 0; i < 4; i++) {
            int idx = tid + i * 256;
            cp16(dst + (idx >> 3) * 9 + (idx & 7), src + (size_t)idx * 16);
        }
        CP_COMMIT();
    }
    // Stage B tile 0 into buf 0 (group 1)
    {
        const char* src = (const char*)g_pb;
        uint4* dst = (uint4*)ps;
        #pragma unroll
        for (int i = 0; i < 4; i++) {
            int idx = tid + i * 256;
            cp16(dst + (idx >> 3) * 9 + (idx & 7), src + (size_t)idx * 16);
        }
        CP_COMMIT();
    }
    // Preload ALL prototype norms + labels (L2-hot, once per CTA)
    #pragma unroll
    for (int i = 0; i < PPTS / 256; i++) {
        int j = tid + i * 256;
        p2s[j] = g_p2[j];
        pls[j] = plab[j];
    }
    // Row labels for this thread's accumulator rows
    int yv[2][2];
    #pragma unroll
    for (int mf = 0; mf < 2; mf++)
        #pragma unroll
        for (int h = 0; h < 2; h++)
            yv[mf][h] = y[rowBase + wm * 32 + mf * 16 + h * 8 + qid];

    float pmin[2][2], nmin[2][2];
    #pragma unroll
    for (int mf = 0; mf < 2; mf++)
        #pragma unroll
        for (int h = 0; h < 2; h++) { pmin[mf][h] = 1e30f; nmin[mf][h] = 1e30f; }

    CP_WAIT(1);        // x tile landed
    __syncthreads();   // (also covers p2s/pls stores)

    // Hoist A fragments: ldmatrix.x4 per (mf, kk) — loop-invariant across P.
    uint32_t a[2][4][4];
    {
        int arow = (lane & 7) + ((lane >> 3) & 1) * 8;
        int acol = (lane >> 4) * 8;
        #pragma unroll
        for (int mf = 0; mf < 2; mf++)
            #pragma unroll
            for (int kk = 0; kk < 4; kk++) {
                uint32_t ad = (uint32_t)__cvta_generic_to_shared(
                    xs + (wm * 32 + mf * 16 + arow) * LDSS + kk * 16 + acol);
                asm volatile(
                    "ldmatrix.sync.aligned.m8n8.x4.shared.b16 {%0,%1,%2,%3}, [%4];\n"
                    : "=r"(a[mf][kk][0]), "=r"(a[mf][kk][1]),
                      "=r"(a[mf][kk][2]), "=r"(a[mf][kk][3]) : "r"(ad));
            }
    }

    const int brow = lane & 7;
    const int bko  = ((lane >> 3) & 1) * 8;

    for (int t = 0; t < NTILES; t++) {
        const int buf = t & 1;
        if (t + 1 < NTILES) {
            __syncthreads();  // everyone done reading buf^1 (tile t-1)
            const char* src = (const char*)(g_pb + (size_t)(t + 1) * BN * DDIM);
            uint4* dst = (uint4*)(ps + (buf ^ 1) * BM * LDSS);
            #pragma unroll
            for (int i = 0; i < 4; i++) {
                int idx = tid + i * 256;
                cp16(dst + (idx >> 3) * 9 + (idx & 7), src + (size_t)idx * 16);
            }
            CP_COMMIT();
            CP_WAIT(1);   // tile t resident
        } else {
            CP_WAIT(0);
        }
        __syncthreads();

        const __nv_bfloat16* pb = ps + buf * BM * LDSS;

        float c[16][4];
        #pragma unroll
        for (int i = 0; i < 16; i++)
            #pragma unroll
            for (int j = 0; j < 4; j++) c[i][j] = 0.f;

        #pragma unroll
        for (int kk = 0; kk < 4; kk++) {
            #pragma unroll
            for (int nf = 0; nf < 8; nf++) {
                uint32_t b0, b1;
                uint32_t bd = (uint32_t)__cvta_generic_to_shared(
                    pb + (wn * 64 + nf * 8 + brow) * LDSS + kk * 16 + bko);
                asm volatile(
                    "ldmatrix.sync.aligned.m8n8.x2.shared.b16 {%0,%1}, [%2];\n"
                    : "=r"(b0), "=r"(b1) : "r"(bd));
                #pragma unroll
                for (int mf = 0; mf < 2; mf++) {
                    float* cc = c[mf * 8 + nf];
                    asm volatile(
                        "mma.sync.aligned.m16n8k16.row.col.f32.bf16.bf16.f32 "
                        "{%0,%1,%2,%3}, {%4,%5,%6,%7}, {%8,%9}, {%0,%1,%2,%3};\n"
                        : "+f"(cc[0]), "+f"(cc[1]), "+f"(cc[2]), "+f"(cc[3])
                        : "r"(a[mf][kk][0]), "r"(a[mf][kk][1]),
                          "r"(a[mf][kk][2]), "r"(a[mf][kk][3]),
                          "r"(b0), "r"(b1));
                }
            }
        }

        // Fused epilogue: s = p2 - 2*dot; masked running mins.
        #pragma unroll
        for (int nf = 0; nf < 8; nf++) {
            const int jc = t * BN + wn * 64 + nf * 8 + qtr * 2;
            float2 pp = *(const float2*)(p2s + jc);
            int2   ll = *(const int2*)(pls + jc);
            #pragma unroll
            for (int mf = 0; mf < 2; mf++) {
                float* cc = c[mf * 8 + nf];
                float s00 = fmaf(-2.f, cc[0], pp.x);
                float s01 = fmaf(-2.f, cc[1], pp.y);
                float s10 = fmaf(-2.f, cc[2], pp.x);
                float s11 = fmaf(-2.f, cc[3], pp.y);
                if (ll.x == yv[mf][0]) pmin[mf][0] = fminf(pmin[mf][0], s00);
                else                   nmin[mf][0] = fminf(nmin[mf][0], s00);
                if (ll.y == yv[mf][0]) pmin[mf][0] = fminf(pmin[mf][0], s01);
                else                   nmin[mf][0] = fminf(nmin[mf][0], s01);
                if (ll.x == yv[mf][1]) pmin[mf][1] = fminf(pmin[mf][1], s10);
                else                   nmin[mf][1] = fminf(nmin[mf][1], s10);
                if (ll.y == yv[mf][1]) pmin[mf][1] = fminf(pmin[mf][1], s11);
                else                   nmin[mf][1] = fminf(nmin[mf][1], s11);
            }
        }
    }

    // Quad reduction (same rows, different cols across 4 lanes).
    #pragma unroll
    for (int mf = 0; mf < 2; mf++)
        #pragma unroll
        for (int h = 0; h < 2; h++) {
            #pragma unroll
            for (int o = 1; o <= 2; o <<= 1) {
                pmin[mf][h] = fminf(pmin[mf][h], __shfl_xor_sync(0xffffffffu, pmin[mf][h], o));
                nmin[mf][h] = fminf(nmin[mf][h], __shfl_xor_sync(0xffffffffu, nmin[mf][h], o));
            }
        }
    if (qtr == 0) {
        #pragma unroll
        for (int mf = 0; mf < 2; mf++)
            #pragma unroll
            for (int h = 0; h < 2; h++) {
                int r = wm * 32 + mf * 16 + h * 8 + qid;
                red[(wn * 2 + 0) * BM + r] = pmin[mf][h];
                red[(wn * 2 + 1) * BM + r] = nmin[mf][h];
            }
    }
    __syncthreads();

    float mysum = 0.f;
    if (tid < BM) {
        float sp = fminf(red[0 * BM + tid], red[2 * BM + tid]);
        float sn = fminf(red[1 * BM + tid], red[3 * BM + tid]);
        float x2 = g_x2[rowBase + tid];
        float pos = sqrtf(fmaxf(sp + x2, 0.f));
        float neg = sqrtf(fmaxf(sn + x2, 0.f));
        float mu = (pos - neg) / (pos + neg);
        mysum = 1.f / (1.f + expf(-mu));
    }
    #pragma unroll
    for (int o = 16; o; o >>= 1) mysum += __shfl_xor_sync(0xffffffffu, mysum, o);
    if (lane == 0) rsum[warp] = mysum;
    __syncthreads();
    if (tid == 0) {
        float s = 0.f;
        #pragma unroll
        for (int i = 0; i < 8; i++) s += rsum[i];
        g_partial[blockIdx.x] = s;
        __threadfence();
        unsigned int ticket = atomicAdd(&g_count, 1);
        *flag = (ticket == gridDim.x - 1) ? 1 : 0;
    }
    __syncthreads();

    // Last block: deterministic final mean (fixed order over fixed array).
    if (*flag) {
        float s = 0.f;
        for (int i = tid; i < NBLOCKS; i += 256) s += __ldcg(&g_partial[i]);
        #pragma unroll
        for (int o = 16; o; o >>= 1) s += __shfl_xor_sync(0xffffffffu, s, o);
        if (lane == 0) rsum[warp] = s;
        __syncthreads();
        if (tid == 0) {
            float tot = 0.f;
            #pragma unroll
            for (int i = 0; i < 8; i++) tot += rsum[i];
            out[0] = tot * (1.0f / (float)NPTS);
            g_count = 0;  // reset for next graph replay
        }
    }
}

extern "C" void kernel_launch(void* const* d_in, const int* in_sizes, int n_in,
                              void* d_out, int out_size) {
    const float* x    = (const float*)d_in[0];
    const int*   y    = (const int*)d_in[1];
    const float* prot = (const float*)d_in[2];
    const int*   plab = (const int*)d_in[3];
    float* out = (float*)d_out;

    const int N = in_sizes[1];   // 65536
    const int P = in_sizes[3];   // 2048

    cudaFuncSetAttribute(glvq_main, cudaFuncAttributeMaxDynamicSharedMemorySize, SM_TOTAL);

    prep_kernel<<<(N + P) / 8, 256>>>(x, prot, N, P);
    glvq_main<<<NBLOCKS, 256, SM_TOTAL>>>(y, plab, out);
}

// round 4
// speedup vs baseline: 1.2265x; 1.1170x over previous
#include <cuda_runtime.h>
#include <cuda_bf16.h>
#include <math.h>
#include <stdint.h>

// Shape (fixed by dataset): N=65536, P=2048, D=64, 10 classes.
#define NPTS 65536
#define PPTS 2048
#define DDIM 64
#define BM 128
#define BN 128
#define LDSS 72              // bf16 per smem row (64 + 8 pad): conflict-free ldmatrix
#define ROWB (LDSS * 2)      // 144 bytes per padded row
#define TILEB (BM * ROWB)    // 18432 bytes per tile buffer
#define NTILES (PPTS / BN)   // 16
#define NBLOCKS (NPTS / BM)  // 512

// __device__ scratch (allocation-free rule)
__device__ __align__(16) __nv_bfloat16 g_xb[NPTS * DDIM];
__device__ __align__(16) __nv_bfloat16 g_pb[PPTS * DDIM];
__device__ float g_x2[NPTS];
__device__ float g_p2[PPTS];
__device__ float g_partial[NBLOCKS];
__device__ unsigned int g_count;   // zero-init; last block resets

// Dynamic smem layout (bytes)
#define SM_B0    0                     // B tile buffer (even t)        18432
#define SM_AB1   18432                 // A tile, then B buffer (odd t) 18432
#define SM_P2    36864                 // 2048 f32                       8192
#define SM_PL    45056                 // 2048 i32                       8192
#define SM_RED   53248                 // [2 grp][2][128] f32            4096
#define SM_RSUM  57344                 // 8 f32
#define SM_FLAG  57376
#define SM_TOTAL 57408

__device__ __forceinline__ void cp16(uint32_t dst, const void* src) {
    asm volatile("cp.async.cg.shared.global [%0], [%1], 16;\n" :: "r"(dst), "l"(src));
}
#define CP_COMMIT() asm volatile("cp.async.commit_group;\n" ::: "memory")
#define CP_WAIT(n)  asm volatile("cp.async.wait_group %0;\n" :: "n"(n) : "memory")

// padded-layout byte offset for the idx-th 16B chunk of a 128x128B tile
__device__ __forceinline__ uint32_t padoff(int idx) {
    return (uint32_t)((idx >> 3) * ROWB + (idx & 7) * 16);
}

// ---------------------------------------------------------------------------
// Prep: fp32 rows (x then prototypes) -> bf16 rows + row sum-of-squares.
// ---------------------------------------------------------------------------
__global__ void prep_kernel(const float* __restrict__ x,
                            const float* __restrict__ p, int N, int P) {
    int warp = (blockIdx.x * blockDim.x + threadIdx.x) >> 5;
    int lane = threadIdx.x & 31;
    if (warp >= N + P) return;
    const float* src; __nv_bfloat162* db; float* d2; int r;
    if (warp < N) { r = warp;     src = x; db = (__nv_bfloat162*)g_xb; d2 = g_x2; }
    else          { r = warp - N; src = p; db = (__nv_bfloat162*)g_pb; d2 = g_p2; }
    float2 v = ((const float2*)(src + (size_t)r * DDIM))[lane];
    float ss = v.x * v.x + v.y * v.y;
    #pragma unroll
    for (int o = 16; o; o >>= 1) ss += __shfl_xor_sync(0xffffffffu, ss, o);
    db[(size_t)r * (DDIM / 2) + lane] = __floats2bfloat162_rn(v.x, v.y);
    if (lane == 0) d2[r] = ss;
}

// ---------------------------------------------------------------------------
// Main: 128x128-tile bf16 mma.sync GEMM fused with masked min + loss.
// nf-major: per 8-col slab do 2 ldmatrix.x4 + 8 MMA + fused epilogue, so
// tensor and ALU pipes overlap across slabs. A frags hoisted; A smem reused
// as second B buffer. One __syncthreads per tile. 3 CTAs/SM.
// ---------------------------------------------------------------------------
__global__ __launch_bounds__(256, 3) void glvq_main(
    const int* __restrict__ y, const int* __restrict__ plab,
    float* __restrict__ out) {

    extern __shared__ char sm[];
    const uint32_t smb = (uint32_t)__cvta_generic_to_shared(sm);
    float* p2s  = (float*)(sm + SM_P2);
    int*   pls  = (int*)(sm + SM_PL);
    float* red  = (float*)(sm + SM_RED);
    float* rsum = (float*)(sm + SM_RSUM);
    int*   flag = (int*)(sm + SM_FLAG);

    const int tid = threadIdx.x;
    const int warp = tid >> 5, lane = tid & 31;
    const int wm = warp >> 1, wn = warp & 1;
    const int qid = lane >> 2, qtr = lane & 3;
    const int rowBase = blockIdx.x * BM;

    // Stage A (group 0) then B0 (group 1), padded layout.
    {
        const char* srcA = (const char*)(g_xb + (size_t)rowBase * DDIM);
        #pragma unroll
        for (int i = 0; i < 4; i++) {
            int c = tid + i * 256;
            cp16(smb + SM_AB1 + padoff(c), srcA + (size_t)c * 16);
        }
        CP_COMMIT();
        #pragma unroll
        for (int i = 0; i < 4; i++) {
            int c = tid + i * 256;
            cp16(smb + SM_B0 + padoff(c), (const char*)g_pb + (size_t)c * 16);
        }
        CP_COMMIT();
    }
    // Prototype norms + labels for all P (L2-hot, once per CTA).
    #pragma unroll
    for (int i = 0; i < PPTS / 256; i++) {
        int j = tid + i * 256;
        p2s[j] = g_p2[j];
        pls[j] = plab[j];
    }
    // Row labels for this thread's accumulator rows.
    int yv[2][2];
    #pragma unroll
    for (int mf = 0; mf < 2; mf++)
        #pragma unroll
        for (int h = 0; h < 2; h++)
            yv[mf][h] = y[rowBase + wm * 32 + mf * 16 + h * 8 + qid];

    float pmin[2][2], nmin[2][2];
    #pragma unroll
    for (int mf = 0; mf < 2; mf++)
        #pragma unroll
        for (int h = 0; h < 2; h++) { pmin[mf][h] = 1e30f; nmin[mf][h] = 1e30f; }

    CP_WAIT(1);        // A resident (B0 still in flight)
    __syncthreads();   // also covers p2s/pls stores

    // Hoist A fragments (loop-invariant across all P tiles): 8x ldmatrix.x4.
    uint32_t a[2][4][4];
    {
        int arow = (lane & 7) + ((lane >> 3) & 1) * 8;
        int acol = (lane >> 4) * 8;
        #pragma unroll
        for (int mf = 0; mf < 2; mf++)
            #pragma unroll
            for (int kk = 0; kk < 4; kk++) {
                uint32_t ad = smb + SM_AB1
                    + (uint32_t)(wm * 32 + mf * 16 + arow) * ROWB
                    + (uint32_t)(kk * 16 + acol) * 2;
                asm volatile(
                    "ldmatrix.sync.aligned.m8n8.x4.shared.b16 {%0,%1,%2,%3}, [%4];\n"
                    : "=r"(a[mf][kk][0]), "=r"(a[mf][kk][1]),
                      "=r"(a[mf][kk][2]), "=r"(a[mf][kk][3]) : "r"(ad));
            }
    }
    __syncthreads();   // A reads done: SM_AB1 is now free to become B buf 1.

    const uint32_t brow_off = (uint32_t)(lane & 7) * ROWB + (uint32_t)((lane >> 3) & 3) * 16;

    for (int t = 0; t < NTILES; t++) {
        CP_WAIT(0);        // B[t] resident
        __syncthreads();   // visible to all; everyone done with B[t-1]'s buffer

        // Prefetch B[t+1] into the other buffer (the one read during t-1).
        if (t + 1 < NTILES) {
            const char* src = (const char*)(g_pb + (size_t)(t + 1) * BN * DDIM);
            uint32_t dstb = smb + (((t + 1) & 1) ? SM_AB1 : SM_B0);
            #pragma unroll
            for (int i = 0; i < 4; i++) {
                int c = tid + i * 256;
                cp16(dstb + padoff(c), src + (size_t)c * 16);
            }
            CP_COMMIT();
        }

        const uint32_t pbase = smb + ((t & 1) ? SM_AB1 : SM_B0)
                             + (uint32_t)(wn * 64) * ROWB + brow_off;

        #pragma unroll
        for (int nf = 0; nf < 8; nf++) {
            // B fragments for all k (two x4 = 8 regs)
            uint32_t b[8];
            uint32_t r0 = pbase + (uint32_t)(nf * 8) * ROWB;
            asm volatile(
                "ldmatrix.sync.aligned.m8n8.x4.shared.b16 {%0,%1,%2,%3}, [%4];\n"
                : "=r"(b[0]), "=r"(b[1]), "=r"(b[2]), "=r"(b[3]) : "r"(r0));
            asm volatile(
                "ldmatrix.sync.aligned.m8n8.x4.shared.b16 {%0,%1,%2,%3}, [%4];\n"
                : "=r"(b[4]), "=r"(b[5]), "=r"(b[6]), "=r"(b[7]) : "r"(r0 + 64));

            float c0[4] = {0.f, 0.f, 0.f, 0.f};
            float c1[4] = {0.f, 0.f, 0.f, 0.f};
            #pragma unroll
            for (int kk = 0; kk < 4; kk++) {
                asm volatile(
                    "mma.sync.aligned.m16n8k16.row.col.f32.bf16.bf16.f32 "
                    "{%0,%1,%2,%3}, {%4,%5,%6,%7}, {%8,%9}, {%0,%1,%2,%3};\n"
                    : "+f"(c0[0]), "+f"(c0[1]), "+f"(c0[2]), "+f"(c0[3])
                    : "r"(a[0][kk][0]), "r"(a[0][kk][1]),
                      "r"(a[0][kk][2]), "r"(a[0][kk][3]),
                      "r"(b[kk * 2]), "r"(b[kk * 2 + 1]));
                asm volatile(
                    "mma.sync.aligned.m16n8k16.row.col.f32.bf16.bf16.f32 "
                    "{%0,%1,%2,%3}, {%4,%5,%6,%7}, {%8,%9}, {%0,%1,%2,%3};\n"
                    : "+f"(c1[0]), "+f"(c1[1]), "+f"(c1[2]), "+f"(c1[3])
                    : "r"(a[1][kk][0]), "r"(a[1][kk][1]),
                      "r"(a[1][kk][2]), "r"(a[1][kk][3]),
                      "r"(b[kk * 2]), "r"(b[kk * 2 + 1]));
            }

            // Fused epilogue for this 8-col slab: s = p2 - 2*dot, masked mins.
            const int jc = t * BN + wn * 64 + nf * 8 + qtr * 2;
            float2 pp = *(const float2*)(p2s + jc);
            int2   ll = *(const int2*)(pls + jc);

            float s00 = fmaf(-2.f, c0[0], pp.x);
            float s01 = fmaf(-2.f, c0[1], pp.y);
            float s02 = fmaf(-2.f, c0[2], pp.x);
            float s03 = fmaf(-2.f, c0[3], pp.y);
            float s10 = fmaf(-2.f, c1[0], pp.x);
            float s11 = fmaf(-2.f, c1[1], pp.y);
            float s12 = fmaf(-2.f, c1[2], pp.x);
            float s13 = fmaf(-2.f, c1[3], pp.y);

            if (ll.x == yv[0][0]) pmin[0][0] = fminf(pmin[0][0], s00);
            else                  nmin[0][0] = fminf(nmin[0][0], s00);
            if (ll.y == yv[0][0]) pmin[0][0] = fminf(pmin[0][0], s01);
            else                  nmin[0][0] = fminf(nmin[0][0], s01);
            if (ll.x == yv[0][1]) pmin[0][1] = fminf(pmin[0][1], s02);
            else                  nmin[0][1] = fminf(nmin[0][1], s02);
            if (ll.y == yv[0][1]) pmin[0][1] = fminf(pmin[0][1], s03);
            else                  nmin[0][1] = fminf(nmin[0][1], s03);
            if (ll.x == yv[1][0]) pmin[1][0] = fminf(pmin[1][0], s10);
            else                  nmin[1][0] = fminf(nmin[1][0], s10);
            if (ll.y == yv[1][0]) pmin[1][0] = fminf(pmin[1][0], s11);
            else                  nmin[1][0] = fminf(nmin[1][0], s11);
            if (ll.x == yv[1][1]) pmin[1][1] = fminf(pmin[1][1], s12);
            else                  nmin[1][1] = fminf(nmin[1][1], s12);
            if (ll.y == yv[1][1]) pmin[1][1] = fminf(pmin[1][1], s13);
            else                  nmin[1][1] = fminf(nmin[1][1], s13);
        }
    }

    // Quad reduction (same rows, different cols across 4 lanes).
    #pragma unroll
    for (int mf = 0; mf < 2; mf++)
        #pragma unroll
        for (int h = 0; h < 2; h++) {
            #pragma unroll
            for (int o = 1; o <= 2; o <<= 1) {
                pmin[mf][h] = fminf(pmin[mf][h], __shfl_xor_sync(0xffffffffu, pmin[mf][h], o));
                nmin[mf][h] = fminf(nmin[mf][h], __shfl_xor_sync(0xffffffffu, nmin[mf][h], o));
            }
        }
    __syncthreads();   // all tile reads done before red[] reuse is irrelevant; ordering only
    if (qtr == 0) {
        #pragma unroll
        for (int mf = 0; mf < 2; mf++)
            #pragma unroll
            for (int h = 0; h < 2; h++) {
                int r = wm * 32 + mf * 16 + h * 8 + qid;
                red[(wn * 2 + 0) * BM + r] = pmin[mf][h];
                red[(wn * 2 + 1) * BM + r] = nmin[mf][h];
            }
    }
    __syncthreads();

    float mysum = 0.f;
    if (tid < BM) {
        float spos = fminf(red[0 * BM + tid], red[2 * BM + tid]);
        float sneg = fminf(red[1 * BM + tid], red[3 * BM + tid]);
        float x2 = g_x2[rowBase + tid];
        float pos = sqrtf(fmaxf(spos + x2, 0.f));
        float neg = sqrtf(fmaxf(sneg + x2, 0.f));
        float mu = (pos - neg) / (pos + neg);
        mysum = 1.f / (1.f + expf(-mu));
    }
    #pragma unroll
    for (int o = 16; o; o >>= 1) mysum += __shfl_xor_sync(0xffffffffu, mysum, o);
    if (lane == 0) rsum[warp] = mysum;
    __syncthreads();
    if (tid == 0) {
        float s = 0.f;
        #pragma unroll
        for (int i = 0; i < 8; i++) s += rsum[i];
        g_partial[blockIdx.x] = s;
        __threadfence();
        unsigned int ticket = atomicAdd(&g_count, 1);
        *flag = (ticket == gridDim.x - 1) ? 1 : 0;
    }
    __syncthreads();

    if (*flag) {   // last block: deterministic final mean
        float s = 0.f;
        for (int i = tid; i < NBLOCKS; i += 256) s += __ldcg(&g_partial[i]);
        #pragma unroll
        for (int o = 16; o; o >>= 1) s += __shfl_xor_sync(0xffffffffu, s, o);
        if (lane == 0) rsum[warp] = s;
        __syncthreads();
        if (tid == 0) {
            float tot = 0.f;
            #pragma unroll
            for (int i = 0; i < 8; i++) tot += rsum[i];
            out[0] = tot * (1.0f / (float)NPTS);
            g_count = 0;   // reset for next graph replay
        }
    }
}

extern "C" void kernel_launch(void* const* d_in, const int* in_sizes, int n_in,
                              void* d_out, int out_size) {
    const float* x    = (const float*)d_in[0];
    const int*   yy   = (const int*)d_in[1];
    const float* prot = (const float*)d_in[2];
    const int*   plab = (const int*)d_in[3];
    float* out = (float*)d_out;

    const int N = in_sizes[1];   // 65536
    const int P = in_sizes[3];   // 2048

    cudaFuncSetAttribute(glvq_main, cudaFuncAttributeMaxDynamicSharedMemorySize, SM_TOTAL);

    prep_kernel<<<(N + P) / 8, 256>>>(x, prot, N, P);
    glvq_main<<<NBLOCKS, 256, SM_TOTAL>>>(yy, plab, out);
}

// round 5
// speedup vs baseline: 1.2271x; 1.0004x over previous
#include <cuda_runtime.h>
#include <cuda_bf16.h>
#include <math.h>
#include <stdint.h>

// Shape (fixed by dataset): N=65536, P=2048, D=64, 10 classes.
#define NPTS 65536
#define PPTS 2048
#define DDIM 64
#define BM 128
#define BN 128
#define LDSS 72              // bf16 per smem row (64 + 8 pad): conflict-free ldmatrix
#define ROWB (LDSS * 2)      // 144 bytes per padded row
#define NTILES (PPTS / BN)   // 16
#define NBLOCKS (NPTS / BM)  // 512

// __device__ scratch (allocation-free rule). Only prototypes need staging now.
__device__ __align__(16) __nv_bfloat16 g_pb[PPTS * DDIM];
__device__ __align__(16) float g_p2[PPTS];
__device__ float g_partial[NBLOCKS];
__device__ unsigned int g_count;   // zero-init; last block resets

// Dynamic smem layout (bytes) — 43.6 KB => 4 CTAs/SM (single wave for 512 CTAs)
#define SM_B0    0                 // B tile buffer (even t)         18432
#define SM_AB1   18432             // A tile, then B buffer (odd t)  18432
#define SM_PP2   36864             // 2 bufs x 128 f32                1024
#define SM_PPL   37888             // 2 bufs x 128 i32                1024
#define SM_RED   38912             // [2 grp][2][128] f32             4096
#define SM_XS2   43008             // 128 f32 row norms                512
#define SM_RSUM  43520             // 8 f32
#define SM_FLAG  43552
#define SM_TOTAL 43584

__device__ __forceinline__ void cp16(uint32_t dst, const void* src) {
    asm volatile("cp.async.cg.shared.global [%0], [%1], 16;\n" :: "r"(dst), "l"(src));
}
#define CP_COMMIT() asm volatile("cp.async.commit_group;\n" ::: "memory")
#define CP_WAIT(n)  asm volatile("cp.async.wait_group %0;\n" :: "n"(n) : "memory")

__device__ __forceinline__ uint32_t padoff(int idx) {     // idx-th 16B chunk
    return (uint32_t)((idx >> 3) * ROWB + (idx & 7) * 16);
}
__device__ __forceinline__ uint32_t pk2(float a, float b) {
    __nv_bfloat162 t = __floats2bfloat162_rn(a, b);
    return *(uint32_t*)&t;
}

// ---------------------------------------------------------------------------
// Prep (prototypes only): fp32 rows -> bf16 rows + row sum-of-squares.
// ---------------------------------------------------------------------------
__global__ void prep_proto(const float* __restrict__ p) {
    int warp = (blockIdx.x * blockDim.x + threadIdx.x) >> 5;
    int lane = threadIdx.x & 31;
    if (warp >= PPTS) return;
    float2 v = ((const float2*)(p + (size_t)warp * DDIM))[lane];
    float ss = v.x * v.x + v.y * v.y;
    #pragma unroll
    for (int o = 16; o; o >>= 1) ss += __shfl_xor_sync(0xffffffffu, ss, o);
    ((__nv_bfloat162*)g_pb)[(size_t)warp * (DDIM / 2) + lane] = __floats2bfloat162_rn(v.x, v.y);
    if (lane == 0) g_p2[warp] = ss;
}

// ---------------------------------------------------------------------------
// Main: 128x128-tile bf16 mma.sync GEMM fused with masked min + loss.
// x converted fp32->bf16 in-kernel (no global bf16 staging for x).
// Per-tile metadata (p2/labels) streamed via cp.async with the B tile.
// 4 CTAs/SM -> 512 CTAs in a single wave.
// ---------------------------------------------------------------------------
__global__ __launch_bounds__(256, 4) void glvq_main(
    const float* __restrict__ x, const int* __restrict__ y,
    const int* __restrict__ plab, float* __restrict__ out) {

    extern __shared__ char sm[];
    const uint32_t smb = (uint32_t)__cvta_generic_to_shared(sm);
    float* red  = (float*)(sm + SM_RED);
    float* xs2  = (float*)(sm + SM_XS2);
    float* rsum = (float*)(sm + SM_RSUM);
    int*   flag = (int*)(sm + SM_FLAG);

    const int tid = threadIdx.x;
    const int warp = tid >> 5, lane = tid & 31;
    const int wm = warp >> 1, wn = warp & 1;
    const int qid = lane >> 2, qtr = lane & 3;
    const int rowBase = blockIdx.x * BM;

    // --- Issue B0 tile + tile-0 metadata via cp.async (overlaps x convert) ---
    {
        #pragma unroll
        for (int i = 0; i < 4; i++) {
            int c = tid + i * 256;
            cp16(smb + SM_B0 + padoff(c), (const char*)g_pb + (size_t)c * 16);
        }
        if (tid < 32)            cp16(smb + SM_PP2 + tid * 16, (const char*)g_p2 + tid * 16);
        else if (tid < 64)       cp16(smb + SM_PPL + (tid - 32) * 16,
                                      (const char*)plab + (tid - 32) * 16);
        CP_COMMIT();
    }

    // --- Convert this CTA's x tile fp32->bf16 into SM_AB1; row norms ---
    {
        const int r = tid >> 1, h = tid & 1;
        const float4* xs4 = (const float4*)(x + (size_t)(rowBase + r) * DDIM + h * 32);
        float ss = 0.f;
        #pragma unroll
        for (int i = 0; i < 4; i++) {
            float4 v0 = xs4[i * 2], v1 = xs4[i * 2 + 1];
            ss += v0.x * v0.x + v0.y * v0.y + v0.z * v0.z + v0.w * v0.w
                + v1.x * v1.x + v1.y * v1.y + v1.z * v1.z + v1.w * v1.w;
            uint4 w;
            w.x = pk2(v0.x, v0.y); w.y = pk2(v0.z, v0.w);
            w.z = pk2(v1.x, v1.y); w.w = pk2(v1.z, v1.w);
            *(uint4*)(sm + SM_AB1 + r * ROWB + h * 64 + i * 16) = w;
        }
        ss += __shfl_xor_sync(0xffffffffu, ss, 1);
        if (h == 0) xs2[r] = ss;
    }

    // Row labels for this thread's accumulator rows.
    int yv[2][2];
    #pragma unroll
    for (int mf = 0; mf < 2; mf++)
        #pragma unroll
        for (int h = 0; h < 2; h++)
            yv[mf][h] = y[rowBase + wm * 32 + mf * 16 + h * 8 + qid];

    float pmin[2][2], nmin[2][2];
    #pragma unroll
    for (int mf = 0; mf < 2; mf++)
        #pragma unroll
        for (int h = 0; h < 2; h++) { pmin[mf][h] = 1e30f; nmin[mf][h] = 1e30f; }

    __syncthreads();   // A tile (STS) + xs2 visible

    // Hoist A fragments (loop-invariant): 8x ldmatrix.x4 from SM_AB1.
    uint32_t a[2][4][4];
    {
        int arow = (lane & 7) + ((lane >> 3) & 1) * 8;
        int acol = (lane >> 4) * 8;
        #pragma unroll
        for (int mf = 0; mf < 2; mf++)
            #pragma unroll
            for (int kk = 0; kk < 4; kk++) {
                uint32_t ad = smb + SM_AB1
                    + (uint32_t)(wm * 32 + mf * 16 + arow) * ROWB
                    + (uint32_t)(kk * 16 + acol) * 2;
                asm volatile(
                    "ldmatrix.sync.aligned.m8n8.x4.shared.b16 {%0,%1,%2,%3}, [%4];\n"
                    : "=r"(a[mf][kk][0]), "=r"(a[mf][kk][1]),
                      "=r"(a[mf][kk][2]), "=r"(a[mf][kk][3]) : "r"(ad));
            }
    }
    __syncthreads();   // A reads done: SM_AB1 becomes B buffer 1.

    const uint32_t brow_off = (uint32_t)(lane & 7) * ROWB + (uint32_t)((lane >> 3) & 3) * 16;

    for (int t = 0; t < NTILES; t++) {
        CP_WAIT(0);        // B[t] + meta[t] resident (this thread's groups)
        __syncthreads();   // visible to all; B[t-1] buffer free

        // Prefetch B[t+1] + meta[t+1] into the other buffer.
        if (t + 1 < NTILES) {
            const char* src = (const char*)(g_pb + (size_t)(t + 1) * BN * DDIM);
            uint32_t dstb = smb + (((t + 1) & 1) ? SM_AB1 : SM_B0);
            #pragma unroll
            for (int i = 0; i < 4; i++) {
                int c = tid + i * 256;
                cp16(dstb + padoff(c), src + (size_t)c * 16);
            }
            uint32_t mb = ((t + 1) & 1) * 512;
            if (tid < 32)
                cp16(smb + SM_PP2 + mb + tid * 16,
                     (const char*)(g_p2 + (size_t)(t + 1) * BN) + tid * 16);
            else if (tid < 64)
                cp16(smb + SM_PPL + mb + (tid - 32) * 16,
                     (const char*)(plab + (size_t)(t + 1) * BN) + (tid - 32) * 16);
            CP_COMMIT();
        }

        const int buf = t & 1;
        const uint32_t pbase = smb + (buf ? SM_AB1 : SM_B0)
                             + (uint32_t)(wn * 64) * ROWB + brow_off;
        const float* pp2 = (const float*)(sm + SM_PP2 + buf * 512);
        const int*   ppl = (const int*)(sm + SM_PPL + buf * 512);

        #pragma unroll
        for (int nf = 0; nf < 8; nf++) {
            uint32_t b[8];
            uint32_t r0 = pbase + (uint32_t)(nf * 8) * ROWB;
            asm volatile(
                "ldmatrix.sync.aligned.m8n8.x4.shared.b16 {%0,%1,%2,%3}, [%4];\n"
                : "=r"(b[0]), "=r"(b[1]), "=r"(b[2]), "=r"(b[3]) : "r"(r0));
            asm volatile(
                "ldmatrix.sync.aligned.m8n8.x4.shared.b16 {%0,%1,%2,%3}, [%4];\n"
                : "=r"(b[4]), "=r"(b[5]), "=r"(b[6]), "=r"(b[7]) : "r"(r0 + 64));

            float c0[4] = {0.f, 0.f, 0.f, 0.f};
            float c1[4] = {0.f, 0.f, 0.f, 0.f};
            #pragma unroll
            for (int kk = 0; kk < 4; kk++) {
                asm volatile(
                    "mma.sync.aligned.m16n8k16.row.col.f32.bf16.bf16.f32 "
                    "{%0,%1,%2,%3}, {%4,%5,%6,%7}, {%8,%9}, {%0,%1,%2,%3};\n"
                    : "+f"(c0[0]), "+f"(c0[1]), "+f"(c0[2]), "+f"(c0[3])
                    : "r"(a[0][kk][0]), "r"(a[0][kk][1]),
                      "r"(a[0][kk][2]), "r"(a[0][kk][3]),
                      "r"(b[kk * 2]), "r"(b[kk * 2 + 1]));
                asm volatile(
                    "mma.sync.aligned.m16n8k16.row.col.f32.bf16.bf16.f32 "
                    "{%0,%1,%2,%3}, {%4,%5,%6,%7}, {%8,%9}, {%0,%1,%2,%3};\n"
                    : "+f"(c1[0]), "+f"(c1[1]), "+f"(c1[2]), "+f"(c1[3])
                    : "r"(a[1][kk][0]), "r"(a[1][kk][1]),
                      "r"(a[1][kk][2]), "r"(a[1][kk][3]),
                      "r"(b[kk * 2]), "r"(b[kk * 2 + 1]));
            }

            // Fused epilogue for this 8-col slab: s = p2 - 2*dot, masked mins.
            const int jc = wn * 64 + nf * 8 + qtr * 2;
            float2 pp = *(const float2*)(pp2 + jc);
            int2   ll = *(const int2*)(ppl + jc);

            float s00 = fmaf(-2.f, c0[0], pp.x);
            float s01 = fmaf(-2.f, c0[1], pp.y);
            float s02 = fmaf(-2.f, c0[2], pp.x);
            float s03 = fmaf(-2.f, c0[3], pp.y);
            float s10 = fmaf(-2.f, c1[0], pp.x);
            float s11 = fmaf(-2.f, c1[1], pp.y);
            float s12 = fmaf(-2.f, c1[2], pp.x);
            float s13 = fmaf(-2.f, c1[3], pp.y);

            if (ll.x == yv[0][0]) pmin[0][0] = fminf(pmin[0][0], s00);
            else                  nmin[0][0] = fminf(nmin[0][0], s00);
            if (ll.y == yv[0][0]) pmin[0][0] = fminf(pmin[0][0], s01);
            else                  nmin[0][0] = fminf(nmin[0][0], s01);
            if (ll.x == yv[0][1]) pmin[0][1] = fminf(pmin[0][1], s02);
            else                  nmin[0][1] = fminf(nmin[0][1], s02);
            if (ll.y == yv[0][1]) pmin[0][1] = fminf(pmin[0][1], s03);
            else                  nmin[0][1] = fminf(nmin[0][1], s03);
            if (ll.x == yv[1][0]) pmin[1][0] = fminf(pmin[1][0], s10);
            else                  nmin[1][0] = fminf(nmin[1][0], s10);
            if (ll.y == yv[1][0]) pmin[1][0] = fminf(pmin[1][0], s11);
            else                  nmin[1][0] = fminf(nmin[1][0], s11);
            if (ll.x == yv[1][1]) pmin[1][1] = fminf(pmin[1][1], s12);
            else                  nmin[1][1] = fminf(nmin[1][1], s12);
            if (ll.y == yv[1][1]) pmin[1][1] = fminf(pmin[1][1], s13);
            else                  nmin[1][1] = fminf(nmin[1][1], s13);
        }
    }

    // Quad reduction (same rows, different cols across 4 lanes).
    #pragma unroll
    for (int mf = 0; mf < 2; mf++)
        #pragma unroll
        for (int h = 0; h < 2; h++) {
            #pragma unroll
            for (int o = 1; o <= 2; o <<= 1) {
                pmin[mf][h] = fminf(pmin[mf][h], __shfl_xor_sync(0xffffffffu, pmin[mf][h], o));
                nmin[mf][h] = fminf(nmin[mf][h], __shfl_xor_sync(0xffffffffu, nmin[mf][h], o));
            }
        }
    __syncthreads();
    if (qtr == 0) {
        #pragma unroll
        for (int mf = 0; mf < 2; mf++)
            #pragma unroll
            for (int h = 0; h < 2; h++) {
                int r = wm * 32 + mf * 16 + h * 8 + qid;
                red[(wn * 2 + 0) * BM + r] = pmin[mf][h];
                red[(wn * 2 + 1) * BM + r] = nmin[mf][h];
            }
    }
    __syncthreads();

    float mysum = 0.f;
    if (tid < BM) {
        float spos = fminf(red[0 * BM + tid], red[2 * BM + tid]);
        float sneg = fminf(red[1 * BM + tid], red[3 * BM + tid]);
        float x2 = xs2[tid];
        float pos = sqrtf(fmaxf(spos + x2, 0.f));
        float neg = sqrtf(fmaxf(sneg + x2, 0.f));
        float mu = (pos - neg) / (pos + neg);
        mysum = 1.f / (1.f + expf(-mu));
    }
    #pragma unroll
    for (int o = 16; o; o >>= 1) mysum += __shfl_xor_sync(0xffffffffu, mysum, o);
    if (lane == 0) rsum[warp] = mysum;
    __syncthreads();
    if (tid == 0) {
        float s = 0.f;
        #pragma unroll
        for (int i = 0; i < 8; i++) s += rsum[i];
        g_partial[blockIdx.x] = s;
        __threadfence();
        unsigned int ticket = atomicAdd(&g_count, 1);
        *flag = (ticket == gridDim.x - 1) ? 1 : 0;
    }
    __syncthreads();

    if (*flag) {   // last block: deterministic final mean
        float s = 0.f;
        for (int i = tid; i < NBLOCKS; i += 256) s += __ldcg(&g_partial[i]);
        #pragma unroll
        for (int o = 16; o; o >>= 1) s += __shfl_xor_sync(0xffffffffu, s, o);
        if (lane == 0) rsum[warp] = s;
        __syncthreads();
        if (tid == 0) {
            float tot = 0.f;
            #pragma unroll
            for (int i = 0; i < 8; i++) tot += rsum[i];
            out[0] = tot * (1.0f / (float)NPTS);
            g_count = 0;   // reset for next graph replay
        }
    }
}

extern "C" void kernel_launch(void* const* d_in, const int* in_sizes, int n_in,
                              void* d_out, int out_size) {
    const float* x    = (const float*)d_in[0];
    const int*   yy   = (const int*)d_in[1];
    const float* prot = (const float*)d_in[2];
    const int*   plab = (const int*)d_in[3];
    float* out = (float*)d_out;

    cudaFuncSetAttribute(glvq_main, cudaFuncAttributeMaxDynamicSharedMemorySize, SM_TOTAL);

    prep_proto<<<PPTS / 8, 256>>>(prot);
    glvq_main<<<NBLOCKS, 256, SM_TOTAL>>>(x, yy, plab, out);
}